// round 14
// baseline (speedup 1.0000x reference)
#include <cuda_runtime.h>
#include <math.h>

#define NN   100000
#define N3   (3 * NN)
#define EE   1600000
#define E3   (3 * EE)
#define XS   64              // padded row stride (256B rows = exactly 2 lines)
#define XS4  16
#define DIN  25
#define DOUT 50
#define SBLK 512
#define NSB  ((N3 + SBLK - 1) / SBLK)   // 586
#define HB   (E3 / 256)                 // 18750 (exact)
#define FOLDB ((150 * 76 + 76 + 255) / 256)  // 45

typedef unsigned long long ull;

// ---------------- f32x2 packed helpers ----------------
__device__ __forceinline__ ull pk2(float x) {
    ull r; asm("mov.b64 %0,{%1,%1};" : "=l"(r) : "f"(x)); return r;
}
__device__ __forceinline__ void fma2(ull& d, ull a, ull b) {
    asm("fma.rn.f32x2 %0,%1,%2,%0;" : "+l"(d) : "l"(a), "l"(b));
}
__device__ __forceinline__ float2 up2(ull v) {
    float2 f; asm("mov.b64 {%0,%1},%2;" : "=f"(f.x), "=f"(f.y) : "l"(v)); return f;
}

// ---------------- scratch ----------------
__device__ __align__(16) float g_xl[3 * NN * XS];   // cols 52..63 never written -> stay 0
__device__ __align__(16) float g_xr[3 * NN * XS];
__device__ __align__(16) float g_out[3 * NN * XS];
__device__ float g_sum[N3];
__device__ float g_att[3][64];
__device__ float g_Wc[150 * 76];
__device__ float g_bc[76];
__device__ int   g_cnt[N3];          // zeroed by k_agg tail for next replay
__device__ int   g_off[N3];          // exclusive offsets; consumed by scatter
__device__ int   g_srcs[E3];
__device__ ull   g_state[NSB];       // lookback scan state; reset by scatter

// ---------------- L0: histogram + att staging --------------------------------
__global__ void k_pre(const int* __restrict__ ei0, const int* __restrict__ ei1,
                      const int* __restrict__ ei2,
                      const float* __restrict__ att0, const float* __restrict__ att1,
                      const float* __restrict__ att2) {
    int b = blockIdx.x;
    if (b < HB) {
        int i = b * 256 + threadIdx.x;
        int tag = i >= 2 * EE ? 2 : (i >= EE ? 1 : 0);
        const int* ei = tag == 0 ? ei0 : (tag == 1 ? ei1 : ei2);
        int l = i - tag * EE;
        int dst = __ldg(ei + EE + l);
        atomicAdd(&g_cnt[tag * NN + dst], 1);
    } else if (threadIdx.x < 192) {
        int t = threadIdx.x >> 6, c = threadIdx.x & 63;
        const float* a = t == 0 ? att0 : (t == 1 ? att1 : att2);
        g_att[t][c] = c < DOUT ? a[c] : 0.f;
    }
}

// ---------------- L1: single-launch decoupled-lookback scan ------------------
__global__ void __launch_bounds__(SBLK) k_scan() {
    __shared__ int s[SBLK];
    __shared__ int pref;
    int b = blockIdx.x, t = threadIdx.x;
    int i = b * SBLK + t;
    int v = i < N3 ? g_cnt[i] : 0;
    s[t] = v;
    __syncthreads();
    for (int o = 1; o < SBLK; o <<= 1) {
        int add = t >= o ? s[t - o] : 0;
        __syncthreads();
        s[t] += add;
        __syncthreads();
    }
    int agg = s[SBLK - 1];
    if (t == 0) {
        atomicExch(&g_state[b], (1ull << 32) | (unsigned)agg);
        int running = 0;
        int idx = b - 1;
        while (idx >= 0) {
            ull st = atomicAdd(&g_state[idx], 0ull);
            unsigned flag = (unsigned)(st >> 32);
            if (flag == 0) continue;
            running += (int)(unsigned)st;
            if (flag == 2) break;
            idx--;
        }
        atomicExch(&g_state[b], (2ull << 32) | (unsigned)(running + agg));
        pref = running;
    }
    __syncthreads();
    if (i < N3) g_off[i] = pref + s[t] - v;
}

// ---------------- L2: scatter + weight fold + state reset --------------------
__global__ void k_scatter(const int* __restrict__ ei0, const int* __restrict__ ei1,
                          const int* __restrict__ ei2,
                          const float* __restrict__ P, const float* __restrict__ pb,
                          const float* __restrict__ W1, const float* __restrict__ b1) {
    int b = blockIdx.x;
    if (b < HB) {
        int i = b * 256 + threadIdx.x;
        int tag = i >= 2 * EE ? 2 : (i >= EE ? 1 : 0);
        const int* ei = tag == 0 ? ei0 : (tag == 1 ? ei1 : ei2);
        int l = i - tag * EE;
        int src = __ldg(ei + l);
        int dst = __ldg(ei + EE + l);
        int slot = atomicAdd(&g_off[tag * NN + dst], 1);
        g_srcs[slot] = src;
    } else {
        if (b == HB)
            for (int i = threadIdx.x; i < NSB; i += 256) g_state[i] = 0;
        int idx = (b - HB) * 256 + threadIdx.x;
        if (idx < 150 * 76) {
            int k = idx / 76, j = idx % 76;
            float a = 0.f;
            if (j < 75) for (int m = 0; m < 150; m++) a += P[k * 150 + m] * W1[m * 75 + j];
            g_Wc[idx] = a;
        } else if (idx < 150 * 76 + 76) {
            int j = idx - 150 * 76;
            float a = 0.f;
            if (j < 75) { a = b1[j]; for (int m = 0; m < 150; m++) a += pb[m] * W1[m * 75 + j]; }
            g_bc[j] = a;
        }
    }
}

// ---------------- L3: node transforms, one w per block (grid.y = 6) ----------
#define K1T 256
#define TS1 66    // tile stride in floats (8B-aligned, bank-clean)
__global__ void __launch_bounds__(K1T) k1(const float* __restrict__ x,
                   const float* __restrict__ Wl0, const float* __restrict__ bl0,
                   const float* __restrict__ Wr0, const float* __restrict__ br0,
                   const float* __restrict__ Wl1, const float* __restrict__ bl1,
                   const float* __restrict__ Wr1, const float* __restrict__ br1,
                   const float* __restrict__ Wl2, const float* __restrict__ bl2,
                   const float* __restrict__ Wr2, const float* __restrict__ br2) {
    __shared__ __align__(16) float sW[DIN * DOUT];
    __shared__ __align__(16) float sb[DOUT];
    extern __shared__ __align__(16) float til[];   // K1T * TS1 floats (67.6 KB dyn)
    int tid = threadIdx.x;
    int w = blockIdx.y;                            // 0..5
    int t = w >> 1;
    {
        const float* Ws = w == 0 ? Wl0 : (w == 1 ? Wr0 : (w == 2 ? Wl1 :
                          (w == 3 ? Wr1 : (w == 4 ? Wl2 : Wr2))));
        const float* bs = w == 0 ? bl0 : (w == 1 ? br0 : (w == 2 ? bl1 :
                          (w == 3 ? br1 : (w == 4 ? bl2 : br2))));
        for (int i = tid; i < DIN * DOUT; i += K1T) sW[i] = Ws[i];
        if (tid < DOUT) sb[tid] = bs[tid];
    }
    int nb = blockIdx.x * K1T;
    for (int i = tid; i < K1T * DIN; i += K1T) {
        int g = nb * DIN + i;
        til[i] = g < NN * DIN ? x[g] : 0.f;
    }
    __syncthreads();
    float xv[DIN];
#pragma unroll
    for (int k = 0; k < DIN; k++) xv[k] = til[tid * DIN + k];
    __syncthreads();   // all reads done before tile reuse

    int rows = min(K1T, NN - nb);

    const ull* Wp = reinterpret_cast<const ull*>(sW);
    const ull* bp = reinterpret_cast<const ull*>(sb);
    ull acc[25];
#pragma unroll
    for (int j = 0; j < 25; j++) acc[j] = bp[j];
#pragma unroll
    for (int k = 0; k < DIN; k++) {
        ull xk2 = pk2(xv[k]);
        const ull* wr = &Wp[k * 25];
#pragma unroll
        for (int j = 0; j < 25; j++) fma2(acc[j], xk2, wr[j]);
    }
    float* trow = til + tid * TS1;
#pragma unroll
    for (int j = 0; j < 25; j++)
        *reinterpret_cast<ull*>(trow + 2 * j) = acc[j];
    *reinterpret_cast<ull*>(trow + 50) = 0ull;     // cols 50,51
    __syncthreads();
    float* dstbase = ((w & 1) ? g_xr : g_xl) + (t * NN + nb) * XS;
    for (int idx = tid; idx < K1T * 26; idx += K1T) {
        int row = idx / 26, ch = idx % 26;
        if (row < rows) {
            ull v = *reinterpret_cast<const ull*>(til + row * TS1 + ch * 2);
            *reinterpret_cast<ull*>(dstbase + row * XS + ch * 2) = v;
        }
    }
}

// ---------------- L4: CSR aggregation: 8 edges/iter, dual accumulators -------
__global__ void __launch_bounds__(256) k_agg() {
    int gid = (blockIdx.x * 256 + threadIdx.x) >> 5;
    if (gid >= N3) return;
    int lane = threadIdx.x & 31;
    int g = lane >> 3, l = lane & 7;           // 4 edge-groups of 8 lanes
    bool two = l < 5;
    int tag = gid >= 2 * NN ? 2 : (gid >= NN ? 1 : 0);
    int nloc = gid - tag * NN;

    const float4* xlb = reinterpret_cast<const float4*>(g_xl) + tag * NN * XS4;
    const float4* xrr = reinterpret_cast<const float4*>(g_xr) + gid * XS4;

    float4 z = make_float4(0.f, 0.f, 0.f, 0.f);
    float4 xr0 = __ldg(xrr + l);
    float4 xr1 = two ? __ldg(xrr + 8 + l) : z;
    float4 at0 = *reinterpret_cast<const float4*>(&g_att[tag][l * 4]);
    float4 at1 = two ? *reinterpret_cast<const float4*>(&g_att[tag][(8 + l) * 4]) : z;

    int e1 = __ldg(&g_off[gid]);               // inclusive end (post-scatter)
    int e0 = gid ? __ldg(&g_off[gid - 1]) : 0;
    int deg = e1 - e0 + 1;                     // + self loop (virtual idx 0)

    float sumA = 0.f, sumB = 0.f;
    float4 a0A = z, a1A = z, a0B = z, a1B = z;

    for (int base = 0; base < deg; base += 32) {
        int idx = base + lane;
        int sv = 0;
        if (idx < deg) sv = idx == 0 ? nloc : __ldg(&g_srcs[e0 + idx - 1]);
        int m = min(32, deg - base);
        for (int i = 0; i < m; i += 8) {
            int eA = i + g;                     // wave A: edges i..i+3
            int eB = i + 4 + g;                 // wave B: edges i+4..i+7 (<=31)
            int sA = __shfl_sync(0xffffffffu, sv, eA);
            int sB = __shfl_sync(0xffffffffu, sv, eB);
            bool evA = eA < m, evB = eB < m;
            const float4* rowA = xlb + sA * XS4;
            const float4* rowB = xlb + sB * XS4;
            float4 w0a = __ldg(rowA + l);
            float4 w0b = __ldg(rowB + l);
            float4 w1a = two ? __ldg(rowA + 8 + l) : z;
            float4 w1b = two ? __ldg(rowB + 8 + l) : z;

            float a, scA = 0.f, scB = 0.f;
            a = w0a.x + xr0.x; a = a > 0.f ? a : 0.2f * a; scA += a * at0.x;
            a = w0b.x + xr0.x; a = a > 0.f ? a : 0.2f * a; scB += a * at0.x;
            a = w0a.y + xr0.y; a = a > 0.f ? a : 0.2f * a; scA += a * at0.y;
            a = w0b.y + xr0.y; a = a > 0.f ? a : 0.2f * a; scB += a * at0.y;
            a = w0a.z + xr0.z; a = a > 0.f ? a : 0.2f * a; scA += a * at0.z;
            a = w0b.z + xr0.z; a = a > 0.f ? a : 0.2f * a; scB += a * at0.z;
            a = w0a.w + xr0.w; a = a > 0.f ? a : 0.2f * a; scA += a * at0.w;
            a = w0b.w + xr0.w; a = a > 0.f ? a : 0.2f * a; scB += a * at0.w;
            a = w1a.x + xr1.x; a = a > 0.f ? a : 0.2f * a; scA += a * at1.x;
            a = w1b.x + xr1.x; a = a > 0.f ? a : 0.2f * a; scB += a * at1.x;
            a = w1a.y + xr1.y; a = a > 0.f ? a : 0.2f * a; scA += a * at1.y;
            a = w1b.y + xr1.y; a = a > 0.f ? a : 0.2f * a; scB += a * at1.y;
            a = w1a.z + xr1.z; a = a > 0.f ? a : 0.2f * a; scA += a * at1.z;
            a = w1b.z + xr1.z; a = a > 0.f ? a : 0.2f * a; scB += a * at1.z;
            a = w1a.w + xr1.w; a = a > 0.f ? a : 0.2f * a; scA += a * at1.w;
            a = w1b.w + xr1.w; a = a > 0.f ? a : 0.2f * a; scB += a * at1.w;

            scA += __shfl_xor_sync(0xffffffffu, scA, 1);
            scB += __shfl_xor_sync(0xffffffffu, scB, 1);
            scA += __shfl_xor_sync(0xffffffffu, scA, 2);
            scB += __shfl_xor_sync(0xffffffffu, scB, 2);
            scA += __shfl_xor_sync(0xffffffffu, scA, 4);
            scB += __shfl_xor_sync(0xffffffffu, scB, 4);

            float eEA = evA ? __expf(scA) : 0.f;
            float eEB = evB ? __expf(scB) : 0.f;
            sumA += eEA;
            sumB += eEB;
            a0A.x += eEA * w0a.x; a0A.y += eEA * w0a.y;
            a0A.z += eEA * w0a.z; a0A.w += eEA * w0a.w;
            a1A.x += eEA * w1a.x; a1A.y += eEA * w1a.y;
            a1A.z += eEA * w1a.z; a1A.w += eEA * w1a.w;
            a0B.x += eEB * w0b.x; a0B.y += eEB * w0b.y;
            a0B.z += eEB * w0b.z; a0B.w += eEB * w0b.w;
            a1B.x += eEB * w1b.x; a1B.y += eEB * w1b.y;
            a1B.z += eEB * w1b.z; a1B.w += eEB * w1b.w;
        }
    }
    // merge waves, then combine the 4 edge-groups (xor over g bits only)
    float4 a0 = make_float4(a0A.x + a0B.x, a0A.y + a0B.y, a0A.z + a0B.z, a0A.w + a0B.w);
    float4 a1 = make_float4(a1A.x + a1B.x, a1A.y + a1B.y, a1A.z + a1B.z, a1A.w + a1B.w);
    float sum = sumA + sumB;
#pragma unroll
    for (int o = 8; o <= 16; o <<= 1) {
        a0.x += __shfl_xor_sync(0xffffffffu, a0.x, o);
        a0.y += __shfl_xor_sync(0xffffffffu, a0.y, o);
        a0.z += __shfl_xor_sync(0xffffffffu, a0.z, o);
        a0.w += __shfl_xor_sync(0xffffffffu, a0.w, o);
        a1.x += __shfl_xor_sync(0xffffffffu, a1.x, o);
        a1.y += __shfl_xor_sync(0xffffffffu, a1.y, o);
        a1.z += __shfl_xor_sync(0xffffffffu, a1.z, o);
        a1.w += __shfl_xor_sync(0xffffffffu, a1.w, o);
        sum  += __shfl_xor_sync(0xffffffffu, sum, o);
    }
    if (lane < 8) {
        float4* orow = reinterpret_cast<float4*>(g_out) + gid * XS4;
        orow[l] = a0;
        if (two) orow[8 + l] = a1;
    }
    if (lane == 8) g_sum[gid] = sum;
    if (lane == 9) g_cnt[gid] = 0;             // reset histogram for next replay
}

// ---------------- L5: head with block-staged tile (f32x2) --------------------
#define K4N 256
#define TSTR 53
__global__ void __launch_bounds__(K4N, 2) k4(
        const float* __restrict__ bo_p, const float* __restrict__ bo_s,
        const float* __restrict__ bo_v,
        const float* __restrict__ W2, const float* __restrict__ b2,
        const float* __restrict__ W3, const float* __restrict__ b3,
        float* __restrict__ out) {
    extern __shared__ __align__(16) float sm4[];
    float* sWc  = sm4;                // 11400 (150 x 76)
    float* sbc  = sWc + 11400;        // 76
    float* sW2  = sbc + 76;           // 2250
    float* sb2  = sW2 + 2250;         // 30
    float* sW3  = sb2 + 30;           // 60
    float* sb3  = sW3 + 60;           // 2
    float* sbo  = sb3 + 2;            // 3 * 52 (cols 50,51 zero)
    float* sinv = sbo + 156;          // 3 * K4N
    float* tile = sinv + 3 * K4N;     // K4N * TSTR

    int tid = threadIdx.x;
    int nb = blockIdx.x * K4N;
    for (int i = tid; i < 11400; i += K4N) sWc[i] = g_Wc[i];
    for (int i = tid; i < 2250;  i += K4N) sW2[i] = W2[i];
    if (tid < 76) sbc[tid] = g_bc[tid];
    if (tid < 30) sb2[tid] = b2[tid];
    if (tid < 60) sW3[tid] = W3[tid];
    if (tid < 2)  sb3[tid] = b3[tid];
    if (tid < 156) {
        int t = tid / 52, c = tid % 52;
        const float* bo = t == 0 ? bo_p : (t == 1 ? bo_s : bo_v);
        sbo[tid] = c < DOUT ? bo[c] : 0.f;
    }
    for (int i = tid; i < 3 * K4N; i += K4N) {
        int t = i / K4N, r = i % K4N;
        int n = nb + r;
        sinv[i] = n < NN ? 1.f / (g_sum[t * NN + n] + 1e-16f) : 0.f;
    }
    __syncthreads();

    ull acc[38];
    const ull* bc64 = reinterpret_cast<const ull*>(sbc);
#pragma unroll
    for (int j = 0; j < 38; j++) acc[j] = bc64[j];

    for (int t = 0; t < 3; t++) {
        for (int idx = tid; idx < K4N * 52; idx += K4N) {
            int row = idx / 52, c = idx % 52;
            int n = nb + row;
            float v = 0.f;
            if (n < NN)
                v = g_out[(t * NN + n) * XS + c] * sinv[t * K4N + row] + sbo[t * 52 + c];
            tile[row * TSTR + c] = v > 0.f ? v : 0.1f * v;
        }
        __syncthreads();
        const float* hrow = &tile[tid * TSTR];
        const float* wbase = &sWc[t * 50 * 76];
        for (int k = 0; k < 50; k++) {
            ull h2 = pk2(hrow[k]);
            const ulonglong2* wr = reinterpret_cast<const ulonglong2*>(wbase + k * 76);
#pragma unroll
            for (int j = 0; j < 19; j++) {
                ulonglong2 w2 = wr[j];
                fma2(acc[2 * j],     h2, w2.x);
                fma2(acc[2 * j + 1], h2, w2.y);
            }
        }
        __syncthreads();
    }

    int n = nb + tid;
    if (n >= NN) return;

    ull acc3[15];
    const ull* b2p = reinterpret_cast<const ull*>(sb2);
#pragma unroll
    for (int j = 0; j < 15; j++) acc3[j] = b2p[j];
#pragma unroll
    for (int kp = 0; kp < 38; kp++) {
        float2 f = up2(acc[kp]);
        {
            float v = f.x > 0.f ? f.x : 0.1f * f.x;
            ull h2 = pk2(v);
            const ull* wr = reinterpret_cast<const ull*>(&sW2[(2 * kp) * 30]);
#pragma unroll
            for (int j = 0; j < 15; j++) fma2(acc3[j], h2, wr[j]);
        }
        if (kp < 37) {
            float v = f.y > 0.f ? f.y : 0.1f * f.y;
            ull h2 = pk2(v);
            const ull* wr = reinterpret_cast<const ull*>(&sW2[(2 * kp + 1) * 30]);
#pragma unroll
            for (int j = 0; j < 15; j++) fma2(acc3[j], h2, wr[j]);
        }
    }

    float o0 = sb3[0], o1 = sb3[1];
#pragma unroll
    for (int j = 0; j < 15; j++) {
        float2 f = up2(acc3[j]);
        float v = f.x > 0.f ? f.x : 0.1f * f.x;
        o0 += v * sW3[(2 * j) * 2];
        o1 += v * sW3[(2 * j) * 2 + 1];
        v = f.y > 0.f ? f.y : 0.1f * f.y;
        o0 += v * sW3[(2 * j + 1) * 2];
        o1 += v * sW3[(2 * j + 1) * 2 + 1];
    }
    *reinterpret_cast<float2*>(&out[n * 2]) = make_float2(o0, o1);
}

// ---------------- launch -----------------------------------------------------
extern "C" void kernel_launch(void* const* d_in, const int* in_sizes, int n_in,
                              void* d_out, int out_size) {
    const float* x    = (const float*)d_in[0];
    const int*   eis[3] = {(const int*)d_in[1], (const int*)d_in[2], (const int*)d_in[3]};
    const float *Wl[3], *bl[3], *Wr[3], *br[3], *att[3], *bo[3];
    int i = 4;
    for (int t = 0; t < 3; t++) {
        Wl[t]  = (const float*)d_in[i++];
        bl[t]  = (const float*)d_in[i++];
        Wr[t]  = (const float*)d_in[i++];
        br[t]  = (const float*)d_in[i++];
        att[t] = (const float*)d_in[i++];
        bo[t]  = (const float*)d_in[i++];
    }
    const float* proj_W = (const float*)d_in[22];
    const float* proj_b = (const float*)d_in[23];
    const float* cls_W1 = (const float*)d_in[24];
    const float* cls_b1 = (const float*)d_in[25];
    const float* cls_W2 = (const float*)d_in[26];
    const float* cls_b2 = (const float*)d_in[27];
    const float* cls_W3 = (const float*)d_in[28];
    const float* cls_b3 = (const float*)d_in[29];
    float* out = (float*)d_out;

    const int SMEM_K4 = (11400 + 76 + 2250 + 30 + 60 + 2 + 156 + 3 * K4N + K4N * TSTR) * 4;
    const int SMEM_K1 = K1T * TS1 * 4;   // 67584 B dynamic
    cudaFuncSetAttribute(k4, cudaFuncAttributeMaxDynamicSharedMemorySize, SMEM_K4);
    cudaFuncSetAttribute(k1, cudaFuncAttributeMaxDynamicSharedMemorySize, SMEM_K1);

    static cudaStream_t s2 = 0;
    static cudaEvent_t evFork = 0, evJoin = 0;
    if (s2 == 0) {
        cudaStreamCreateWithFlags(&s2, cudaStreamNonBlocking);
        cudaEventCreateWithFlags(&evFork, cudaEventDisableTiming);
        cudaEventCreateWithFlags(&evJoin, cudaEventDisableTiming);
    }

    dim3 g1((NN + K1T - 1) / K1T, 6);

    // fork: k1 (independent of the edge-sort chain) runs on s2
    cudaEventRecord(evFork, 0);
    cudaStreamWaitEvent(s2, evFork, 0);
    k1<<<g1, K1T, SMEM_K1, s2>>>(x,
                                 Wl[0], bl[0], Wr[0], br[0],
                                 Wl[1], bl[1], Wr[1], br[1],
                                 Wl[2], bl[2], Wr[2], br[2]);
    cudaEventRecord(evJoin, s2);

    // main stream: edge-sort chain
    k_pre<<<HB + 1, 256>>>(eis[0], eis[1], eis[2], att[0], att[1], att[2]);
    k_scan<<<NSB, SBLK>>>();
    k_scatter<<<HB + FOLDB, 256>>>(eis[0], eis[1], eis[2],
                                   proj_W, proj_b, cls_W1, cls_b1);
    cudaStreamWaitEvent(0, evJoin, 0);
    k_agg<<<(N3 * 32 + 255) / 256, 256>>>();
    k4<<<(NN + K4N - 1) / K4N, K4N, SMEM_K4>>>(bo[0], bo[1], bo[2],
                                               cls_W2, cls_b2, cls_W3, cls_b3, out);
}

// round 15
// speedup vs baseline: 1.1735x; 1.1735x over previous
#include <cuda_runtime.h>
#include <math.h>

#define NN   100000
#define N3   (3 * NN)
#define EE   1600000
#define E3   (3 * EE)
#define XS   64              // padded row stride (256B rows = exactly 2 lines)
#define XS4  16
#define DIN  25
#define DOUT 50
#define SBLK 512
#define NSB  ((N3 + SBLK - 1) / SBLK)   // 586
#define HB   (E3 / 256)                 // 18750 (exact)
#define FOLDB ((150 * 76 + 76 + 255) / 256)  // 45

typedef unsigned long long ull;

// ---------------- f32x2 packed helpers ----------------
__device__ __forceinline__ ull pk2(float x) {
    ull r; asm("mov.b64 %0,{%1,%1};" : "=l"(r) : "f"(x)); return r;
}
__device__ __forceinline__ void fma2(ull& d, ull a, ull b) {
    asm("fma.rn.f32x2 %0,%1,%2,%0;" : "+l"(d) : "l"(a), "l"(b));
}
__device__ __forceinline__ float2 up2(ull v) {
    float2 f; asm("mov.b64 {%0,%1},%2;" : "=f"(f.x), "=f"(f.y) : "l"(v)); return f;
}

// ---------------- scratch ----------------
__device__ __align__(16) float g_xl[3 * NN * XS];   // cols 52..63 never written -> stay 0
__device__ __align__(16) float g_xr[3 * NN * XS];
__device__ __align__(16) float g_out[3 * NN * XS];
__device__ float g_sum[N3];
__device__ float g_att[3][64];
__device__ float g_Wc[150 * 76];
__device__ float g_bc[76];
__device__ int   g_cnt[N3];          // zeroed by k_agg tail for next replay
__device__ int   g_off[N3];          // exclusive offsets; consumed by scatter
__device__ int   g_srcs[E3];
__device__ ull   g_state[NSB];       // lookback scan state; reset by scatter

// ---------------- L0: histogram + att staging --------------------------------
__global__ void k_pre(const int* __restrict__ ei0, const int* __restrict__ ei1,
                      const int* __restrict__ ei2,
                      const float* __restrict__ att0, const float* __restrict__ att1,
                      const float* __restrict__ att2) {
    int b = blockIdx.x;
    if (b < HB) {
        int i = b * 256 + threadIdx.x;
        int tag = i >= 2 * EE ? 2 : (i >= EE ? 1 : 0);
        const int* ei = tag == 0 ? ei0 : (tag == 1 ? ei1 : ei2);
        int l = i - tag * EE;
        int dst = __ldg(ei + EE + l);
        atomicAdd(&g_cnt[tag * NN + dst], 1);
    } else if (threadIdx.x < 192) {
        int t = threadIdx.x >> 6, c = threadIdx.x & 63;
        const float* a = t == 0 ? att0 : (t == 1 ? att1 : att2);
        g_att[t][c] = c < DOUT ? a[c] : 0.f;
    }
}

// ---------------- L1: single-launch decoupled-lookback scan ------------------
__global__ void __launch_bounds__(SBLK) k_scan() {
    __shared__ int s[SBLK];
    __shared__ int pref;
    int b = blockIdx.x, t = threadIdx.x;
    int i = b * SBLK + t;
    int v = i < N3 ? g_cnt[i] : 0;
    s[t] = v;
    __syncthreads();
    for (int o = 1; o < SBLK; o <<= 1) {
        int add = t >= o ? s[t - o] : 0;
        __syncthreads();
        s[t] += add;
        __syncthreads();
    }
    int agg = s[SBLK - 1];
    if (t == 0) {
        atomicExch(&g_state[b], (1ull << 32) | (unsigned)agg);
        int running = 0;
        int idx = b - 1;
        while (idx >= 0) {
            ull st = atomicAdd(&g_state[idx], 0ull);
            unsigned flag = (unsigned)(st >> 32);
            if (flag == 0) continue;
            running += (int)(unsigned)st;
            if (flag == 2) break;
            idx--;
        }
        atomicExch(&g_state[b], (2ull << 32) | (unsigned)(running + agg));
        pref = running;
    }
    __syncthreads();
    if (i < N3) g_off[i] = pref + s[t] - v;
}

// ---------------- L2: scatter + weight fold + state reset --------------------
__global__ void k_scatter(const int* __restrict__ ei0, const int* __restrict__ ei1,
                          const int* __restrict__ ei2,
                          const float* __restrict__ P, const float* __restrict__ pb,
                          const float* __restrict__ W1, const float* __restrict__ b1) {
    int b = blockIdx.x;
    if (b < HB) {
        int i = b * 256 + threadIdx.x;
        int tag = i >= 2 * EE ? 2 : (i >= EE ? 1 : 0);
        const int* ei = tag == 0 ? ei0 : (tag == 1 ? ei1 : ei2);
        int l = i - tag * EE;
        int src = __ldg(ei + l);
        int dst = __ldg(ei + EE + l);
        int slot = atomicAdd(&g_off[tag * NN + dst], 1);
        g_srcs[slot] = src;
    } else {
        if (b == HB)
            for (int i = threadIdx.x; i < NSB; i += 256) g_state[i] = 0;
        int idx = (b - HB) * 256 + threadIdx.x;
        if (idx < 150 * 76) {
            int k = idx / 76, j = idx % 76;
            float a = 0.f;
            if (j < 75) for (int m = 0; m < 150; m++) a += P[k * 150 + m] * W1[m * 75 + j];
            g_Wc[idx] = a;
        } else if (idx < 150 * 76 + 76) {
            int j = idx - 150 * 76;
            float a = 0.f;
            if (j < 75) { a = b1[j]; for (int m = 0; m < 150; m++) a += pb[m] * W1[m * 75 + j]; }
            g_bc[j] = a;
        }
    }
}

// ---------------- L3: node transforms, one w per block (grid.y = 6) ----------
#define K1T 256
#define TS1 66    // tile stride in floats (8B-aligned, bank-clean)
__global__ void __launch_bounds__(K1T) k1(const float* __restrict__ x,
                   const float* __restrict__ Wl0, const float* __restrict__ bl0,
                   const float* __restrict__ Wr0, const float* __restrict__ br0,
                   const float* __restrict__ Wl1, const float* __restrict__ bl1,
                   const float* __restrict__ Wr1, const float* __restrict__ br1,
                   const float* __restrict__ Wl2, const float* __restrict__ bl2,
                   const float* __restrict__ Wr2, const float* __restrict__ br2) {
    __shared__ __align__(16) float sW[DIN * DOUT];
    __shared__ __align__(16) float sb[DOUT];
    extern __shared__ __align__(16) float til[];   // K1T * TS1 floats (67.6 KB dyn)
    int tid = threadIdx.x;
    int w = blockIdx.y;                            // 0..5
    int t = w >> 1;
    {
        const float* Ws = w == 0 ? Wl0 : (w == 1 ? Wr0 : (w == 2 ? Wl1 :
                          (w == 3 ? Wr1 : (w == 4 ? Wl2 : Wr2))));
        const float* bs = w == 0 ? bl0 : (w == 1 ? br0 : (w == 2 ? bl1 :
                          (w == 3 ? br1 : (w == 4 ? bl2 : br2))));
        for (int i = tid; i < DIN * DOUT; i += K1T) sW[i] = Ws[i];
        if (tid < DOUT) sb[tid] = bs[tid];
    }
    int nb = blockIdx.x * K1T;
    for (int i = tid; i < K1T * DIN; i += K1T) {
        int g = nb * DIN + i;
        til[i] = g < NN * DIN ? x[g] : 0.f;
    }
    __syncthreads();
    float xv[DIN];
#pragma unroll
    for (int k = 0; k < DIN; k++) xv[k] = til[tid * DIN + k];
    __syncthreads();   // all reads done before tile reuse

    int rows = min(K1T, NN - nb);

    const ull* Wp = reinterpret_cast<const ull*>(sW);
    const ull* bp = reinterpret_cast<const ull*>(sb);
    ull acc[25];
#pragma unroll
    for (int j = 0; j < 25; j++) acc[j] = bp[j];
#pragma unroll
    for (int k = 0; k < DIN; k++) {
        ull xk2 = pk2(xv[k]);
        const ull* wr = &Wp[k * 25];
#pragma unroll
        for (int j = 0; j < 25; j++) fma2(acc[j], xk2, wr[j]);
    }
    float* trow = til + tid * TS1;
#pragma unroll
    for (int j = 0; j < 25; j++)
        *reinterpret_cast<ull*>(trow + 2 * j) = acc[j];
    *reinterpret_cast<ull*>(trow + 50) = 0ull;     // cols 50,51
    __syncthreads();
    float* dstbase = ((w & 1) ? g_xr : g_xl) + (t * NN + nb) * XS;
    for (int idx = tid; idx < K1T * 26; idx += K1T) {
        int row = idx / 26, ch = idx % 26;
        if (row < rows) {
            ull v = *reinterpret_cast<const ull*>(til + row * TS1 + ch * 2);
            *reinterpret_cast<ull*>(dstbase + row * XS + ch * 2) = v;
        }
    }
}

// ---------------- L4: CSR aggregation: warp/node, 8-lane groups, 64-thr blocks
// Small blocks: CTA retires on max of 2 node-degrees (not 8) -> less tail waste.
#define AGT 64
__global__ void __launch_bounds__(AGT) k_agg() {
    int gid = (blockIdx.x * AGT + threadIdx.x) >> 5;
    if (gid >= N3) return;
    int lane = threadIdx.x & 31;
    int g = lane >> 3, l = lane & 7;           // 4 edge-groups of 8 lanes
    bool two = l < 5;
    int tag = gid >= 2 * NN ? 2 : (gid >= NN ? 1 : 0);
    int nloc = gid - tag * NN;

    const float4* xlb = reinterpret_cast<const float4*>(g_xl) + tag * NN * XS4;
    const float4* xrr = reinterpret_cast<const float4*>(g_xr) + gid * XS4;

    float4 z = make_float4(0.f, 0.f, 0.f, 0.f);
    float4 xr0 = __ldg(xrr + l);
    float4 xr1 = two ? __ldg(xrr + 8 + l) : z;
    float4 at0 = *reinterpret_cast<const float4*>(&g_att[tag][l * 4]);
    float4 at1 = two ? *reinterpret_cast<const float4*>(&g_att[tag][(8 + l) * 4]) : z;

    int e1 = __ldg(&g_off[gid]);               // inclusive end (post-scatter)
    int e0 = gid ? __ldg(&g_off[gid - 1]) : 0;
    int deg = e1 - e0 + 1;                     // + self loop (virtual idx 0)

    float sum = 0.f;
    float4 a0 = z, a1 = z;

    for (int base = 0; base < deg; base += 32) {
        int idx = base + lane;
        int sv = 0;
        if (idx < deg) sv = idx == 0 ? nloc : __ldg(&g_srcs[e0 + idx - 1]);
        int m = min(32, deg - base);
        for (int i = 0; i < m; i += 4) {
            int eidx = i + g;
            int s = __shfl_sync(0xffffffffu, sv, eidx);
            bool ev = eidx < m;
            const float4* row = xlb + s * XS4;
            float4 w0 = __ldg(row + l);
            float4 w1 = two ? __ldg(row + 8 + l) : z;
            float a, sc;
            a = w0.x + xr0.x; a = a > 0.f ? a : 0.2f * a; sc  = a * at0.x;
            a = w0.y + xr0.y; a = a > 0.f ? a : 0.2f * a; sc += a * at0.y;
            a = w0.z + xr0.z; a = a > 0.f ? a : 0.2f * a; sc += a * at0.z;
            a = w0.w + xr0.w; a = a > 0.f ? a : 0.2f * a; sc += a * at0.w;
            a = w1.x + xr1.x; a = a > 0.f ? a : 0.2f * a; sc += a * at1.x;
            a = w1.y + xr1.y; a = a > 0.f ? a : 0.2f * a; sc += a * at1.y;
            a = w1.z + xr1.z; a = a > 0.f ? a : 0.2f * a; sc += a * at1.z;
            a = w1.w + xr1.w; a = a > 0.f ? a : 0.2f * a; sc += a * at1.w;
            sc += __shfl_xor_sync(0xffffffffu, sc, 1);
            sc += __shfl_xor_sync(0xffffffffu, sc, 2);
            sc += __shfl_xor_sync(0xffffffffu, sc, 4);
            float e = ev ? __expf(sc) : 0.f;
            sum += e;
            a0.x += e * w0.x; a0.y += e * w0.y; a0.z += e * w0.z; a0.w += e * w0.w;
            a1.x += e * w1.x; a1.y += e * w1.y; a1.z += e * w1.z; a1.w += e * w1.w;
        }
    }
#pragma unroll
    for (int o = 8; o <= 16; o <<= 1) {
        a0.x += __shfl_xor_sync(0xffffffffu, a0.x, o);
        a0.y += __shfl_xor_sync(0xffffffffu, a0.y, o);
        a0.z += __shfl_xor_sync(0xffffffffu, a0.z, o);
        a0.w += __shfl_xor_sync(0xffffffffu, a0.w, o);
        a1.x += __shfl_xor_sync(0xffffffffu, a1.x, o);
        a1.y += __shfl_xor_sync(0xffffffffu, a1.y, o);
        a1.z += __shfl_xor_sync(0xffffffffu, a1.z, o);
        a1.w += __shfl_xor_sync(0xffffffffu, a1.w, o);
        sum  += __shfl_xor_sync(0xffffffffu, sum, o);
    }
    if (lane < 8) {
        float4* orow = reinterpret_cast<float4*>(g_out) + gid * XS4;
        orow[l] = a0;
        if (two) orow[8 + l] = a1;
    }
    if (lane == 8) g_sum[gid] = sum;
    if (lane == 9) g_cnt[gid] = 0;             // reset histogram for next replay
}

// ---------------- L5: head with block-staged tile (f32x2) --------------------
#define K4N 256
#define TSTR 53
__global__ void __launch_bounds__(K4N, 2) k4(
        const float* __restrict__ bo_p, const float* __restrict__ bo_s,
        const float* __restrict__ bo_v,
        const float* __restrict__ W2, const float* __restrict__ b2,
        const float* __restrict__ W3, const float* __restrict__ b3,
        float* __restrict__ out) {
    extern __shared__ __align__(16) float sm4[];
    float* sWc  = sm4;                // 11400 (150 x 76)
    float* sbc  = sWc + 11400;        // 76
    float* sW2  = sbc + 76;           // 2250
    float* sb2  = sW2 + 2250;         // 30
    float* sW3  = sb2 + 30;           // 60
    float* sb3  = sW3 + 60;           // 2
    float* sbo  = sb3 + 2;            // 3 * 52 (cols 50,51 zero)
    float* sinv = sbo + 156;          // 3 * K4N
    float* tile = sinv + 3 * K4N;     // K4N * TSTR

    int tid = threadIdx.x;
    int nb = blockIdx.x * K4N;
    for (int i = tid; i < 11400; i += K4N) sWc[i] = g_Wc[i];
    for (int i = tid; i < 2250;  i += K4N) sW2[i] = W2[i];
    if (tid < 76) sbc[tid] = g_bc[tid];
    if (tid < 30) sb2[tid] = b2[tid];
    if (tid < 60) sW3[tid] = W3[tid];
    if (tid < 2)  sb3[tid] = b3[tid];
    if (tid < 156) {
        int t = tid / 52, c = tid % 52;
        const float* bo = t == 0 ? bo_p : (t == 1 ? bo_s : bo_v);
        sbo[tid] = c < DOUT ? bo[c] : 0.f;
    }
    for (int i = tid; i < 3 * K4N; i += K4N) {
        int t = i / K4N, r = i % K4N;
        int n = nb + r;
        sinv[i] = n < NN ? 1.f / (g_sum[t * NN + n] + 1e-16f) : 0.f;
    }
    __syncthreads();

    ull acc[38];
    const ull* bc64 = reinterpret_cast<const ull*>(sbc);
#pragma unroll
    for (int j = 0; j < 38; j++) acc[j] = bc64[j];

    for (int t = 0; t < 3; t++) {
        for (int idx = tid; idx < K4N * 52; idx += K4N) {
            int row = idx / 52, c = idx % 52;
            int n = nb + row;
            float v = 0.f;
            if (n < NN)
                v = g_out[(t * NN + n) * XS + c] * sinv[t * K4N + row] + sbo[t * 52 + c];
            tile[row * TSTR + c] = v > 0.f ? v : 0.1f * v;
        }
        __syncthreads();
        const float* hrow = &tile[tid * TSTR];
        const float* wbase = &sWc[t * 50 * 76];
        for (int k = 0; k < 50; k++) {
            ull h2 = pk2(hrow[k]);
            const ulonglong2* wr = reinterpret_cast<const ulonglong2*>(wbase + k * 76);
#pragma unroll
            for (int j = 0; j < 19; j++) {
                ulonglong2 w2 = wr[j];
                fma2(acc[2 * j],     h2, w2.x);
                fma2(acc[2 * j + 1], h2, w2.y);
            }
        }
        __syncthreads();
    }

    int n = nb + tid;
    if (n >= NN) return;

    ull acc3[15];
    const ull* b2p = reinterpret_cast<const ull*>(sb2);
#pragma unroll
    for (int j = 0; j < 15; j++) acc3[j] = b2p[j];
#pragma unroll
    for (int kp = 0; kp < 38; kp++) {
        float2 f = up2(acc[kp]);
        {
            float v = f.x > 0.f ? f.x : 0.1f * f.x;
            ull h2 = pk2(v);
            const ull* wr = reinterpret_cast<const ull*>(&sW2[(2 * kp) * 30]);
#pragma unroll
            for (int j = 0; j < 15; j++) fma2(acc3[j], h2, wr[j]);
        }
        if (kp < 37) {
            float v = f.y > 0.f ? f.y : 0.1f * f.y;
            ull h2 = pk2(v);
            const ull* wr = reinterpret_cast<const ull*>(&sW2[(2 * kp + 1) * 30]);
#pragma unroll
            for (int j = 0; j < 15; j++) fma2(acc3[j], h2, wr[j]);
        }
    }

    float o0 = sb3[0], o1 = sb3[1];
#pragma unroll
    for (int j = 0; j < 15; j++) {
        float2 f = up2(acc3[j]);
        float v = f.x > 0.f ? f.x : 0.1f * f.x;
        o0 += v * sW3[(2 * j) * 2];
        o1 += v * sW3[(2 * j) * 2 + 1];
        v = f.y > 0.f ? f.y : 0.1f * f.y;
        o0 += v * sW3[(2 * j + 1) * 2];
        o1 += v * sW3[(2 * j + 1) * 2 + 1];
    }
    *reinterpret_cast<float2*>(&out[n * 2]) = make_float2(o0, o1);
}

// ---------------- launch -----------------------------------------------------
extern "C" void kernel_launch(void* const* d_in, const int* in_sizes, int n_in,
                              void* d_out, int out_size) {
    const float* x    = (const float*)d_in[0];
    const int*   eis[3] = {(const int*)d_in[1], (const int*)d_in[2], (const int*)d_in[3]};
    const float *Wl[3], *bl[3], *Wr[3], *br[3], *att[3], *bo[3];
    int i = 4;
    for (int t = 0; t < 3; t++) {
        Wl[t]  = (const float*)d_in[i++];
        bl[t]  = (const float*)d_in[i++];
        Wr[t]  = (const float*)d_in[i++];
        br[t]  = (const float*)d_in[i++];
        att[t] = (const float*)d_in[i++];
        bo[t]  = (const float*)d_in[i++];
    }
    const float* proj_W = (const float*)d_in[22];
    const float* proj_b = (const float*)d_in[23];
    const float* cls_W1 = (const float*)d_in[24];
    const float* cls_b1 = (const float*)d_in[25];
    const float* cls_W2 = (const float*)d_in[26];
    const float* cls_b2 = (const float*)d_in[27];
    const float* cls_W3 = (const float*)d_in[28];
    const float* cls_b3 = (const float*)d_in[29];
    float* out = (float*)d_out;

    const int SMEM_K4 = (11400 + 76 + 2250 + 30 + 60 + 2 + 156 + 3 * K4N + K4N * TSTR) * 4;
    const int SMEM_K1 = K1T * TS1 * 4;   // 67584 B dynamic
    cudaFuncSetAttribute(k4, cudaFuncAttributeMaxDynamicSharedMemorySize, SMEM_K4);
    cudaFuncSetAttribute(k1, cudaFuncAttributeMaxDynamicSharedMemorySize, SMEM_K1);

    static cudaStream_t s2 = 0;
    static cudaEvent_t evFork = 0, evJoin = 0;
    if (s2 == 0) {
        cudaStreamCreateWithFlags(&s2, cudaStreamNonBlocking);
        cudaEventCreateWithFlags(&evFork, cudaEventDisableTiming);
        cudaEventCreateWithFlags(&evJoin, cudaEventDisableTiming);
    }

    dim3 g1((NN + K1T - 1) / K1T, 6);

    // fork: k1 (independent of the edge-sort chain) runs on s2
    cudaEventRecord(evFork, 0);
    cudaStreamWaitEvent(s2, evFork, 0);
    k1<<<g1, K1T, SMEM_K1, s2>>>(x,
                                 Wl[0], bl[0], Wr[0], br[0],
                                 Wl[1], bl[1], Wr[1], br[1],
                                 Wl[2], bl[2], Wr[2], br[2]);
    cudaEventRecord(evJoin, s2);

    // main stream: edge-sort chain
    k_pre<<<HB + 1, 256>>>(eis[0], eis[1], eis[2], att[0], att[1], att[2]);
    k_scan<<<NSB, SBLK>>>();
    k_scatter<<<HB + FOLDB, 256>>>(eis[0], eis[1], eis[2],
                                   proj_W, proj_b, cls_W1, cls_b1);
    cudaStreamWaitEvent(0, evJoin, 0);
    k_agg<<<(N3 * 32 + AGT - 1) / AGT, AGT>>>();
    k4<<<(NN + K4N - 1) / K4N, K4N, SMEM_K4>>>(bo[0], bo[1], bo[2],
                                               cls_W2, cls_b2, cls_W3, cls_b3, out);
}